// round 15
// baseline (speedup 1.0000x reference)
#include <cuda_runtime.h>
#include <cuda_fp16.h>
#include <math.h>
#include <cstdint>

#define NB 4
#define NC 256
#define HW 4096
#define NHEADS 4
#define HD 64

// Scratch (allocation-free rule: __device__ globals)
__device__ __half g_x16[(size_t)NB * NC * HW];        // fp16 copy of x
__device__ __half g_wq16[768 * 256];                  // fp16 w_qkv
__device__ __half g_wo16[256 * 256];                  // fp16 w_out
__device__ __half g_qkv16[(size_t)NB * 3 * NC * HW];  // [b][o(768)][hw]
__device__ __half g_att16[(size_t)NB * NC * HW];      // [b][c][hw]

// ---------------- helpers ----------------
__device__ __forceinline__ unsigned pkhf2(float lo, float hi) {
    unsigned r;
    asm("cvt.rn.f16x2.f32 %0, %1, %2;" : "=r"(r) : "f"(hi), "f"(lo));
    return r;
}
__device__ __forceinline__ unsigned hfma2u(unsigned a, unsigned b, unsigned c) {
    unsigned d;
    asm("fma.rn.f16x2 %0, %1, %2, %3;" : "=r"(d) : "r"(a), "r"(b), "r"(c));
    return d;
}
__device__ __forceinline__ unsigned h2ex2u(unsigned a) {
    unsigned d;
    asm("ex2.approx.f16x2 %0, %1;" : "=r"(d) : "r"(a));
    return d;
}
__device__ __forceinline__ void mma_f16(float c[4], const unsigned a[4],
                                        unsigned b0, unsigned b1) {
    asm volatile(
        "mma.sync.aligned.m16n8k16.row.col.f32.f16.f16.f32 "
        "{%0,%1,%2,%3}, {%4,%5,%6,%7}, {%8,%9}, {%0,%1,%2,%3};"
        : "+f"(c[0]), "+f"(c[1]), "+f"(c[2]), "+f"(c[3])
        : "r"(a[0]), "r"(a[1]), "r"(a[2]), "r"(a[3]), "r"(b0), "r"(b1));
}
__device__ __forceinline__ void cpa16(void* dst, const void* src) {
    unsigned d = (unsigned)__cvta_generic_to_shared(dst);
    asm volatile("cp.async.cg.shared.global [%0], [%1], 16;" ::"r"(d), "l"(src));
}
#define CP_COMMIT asm volatile("cp.async.commit_group;")
#define CP_WAIT(n) asm volatile("cp.async.wait_group %0;" ::"n"(n))

__device__ __forceinline__ unsigned smem_u32(const void* p) {
    return (unsigned)__cvta_generic_to_shared(p);
}
__device__ __forceinline__ void ldsm4t(unsigned r[4], unsigned addr) {
    asm volatile(
        "ldmatrix.sync.aligned.m8n8.x4.trans.shared.b16 {%0,%1,%2,%3}, [%4];"
        : "=r"(r[0]), "=r"(r[1]), "=r"(r[2]), "=r"(r[3])
        : "r"(addr));
}
__device__ __forceinline__ void ldsm4(unsigned r[4], unsigned addr) {
    asm volatile(
        "ldmatrix.sync.aligned.m8n8.x4.shared.b16 {%0,%1,%2,%3}, [%4];"
        : "=r"(r[0]), "=r"(r[1]), "=r"(r[2]), "=r"(r[3])
        : "r"(addr));
}

// ---------------- fp32 -> fp16 convert (all three tensors, one launch) ------
#define CVT_N0 (NB * NC * HW / 4)
#define CVT_N1 (768 * 256 / 4)
#define CVT_N2 (256 * 256 / 4)
#define CVT_TOT (CVT_N0 + CVT_N1 + CVT_N2)

__global__ void cvt3_k(const float* __restrict__ x, __half* __restrict__ x16,
                       const float* __restrict__ wq, __half* __restrict__ wq16,
                       const float* __restrict__ wo, __half* __restrict__ wo16) {
    int i = blockIdx.x * 256 + threadIdx.x;
    const float* src;
    __half* dst;
    if (i < CVT_N0) {
        src = x; dst = x16;
    } else if (i < CVT_N0 + CVT_N1) {
        i -= CVT_N0; src = wq; dst = wq16;
    } else if (i < CVT_TOT) {
        i -= CVT_N0 + CVT_N1; src = wo; dst = wo16;
    } else {
        return;
    }
    float4 v = ((const float4*)src)[i];
    ((uint2*)dst)[i] = make_uint2(pkhf2(v.x, v.y), pkhf2(v.z, v.w));
}

// ================ fp16 tensor-core GEMM (BK=32, 3-stage ring) ================
#define GA_PITCH 40
#define GB_PITCH 136
#define GA_HALFS (128 * GA_PITCH)
#define GB_HALFS (32 * GB_PITCH)
#define GEMM_SMEM (3 * (GA_HALFS + GB_HALFS) * 2)

template <int M, bool EPI, bool HALF_OUT>
__global__ __launch_bounds__(256, 2) void gemm_f16(
    const __half* __restrict__ W, const __half* __restrict__ X,
    const float* __restrict__ bias, const float* __restrict__ R,
    void* __restrict__ Yv) {
    extern __shared__ __half smh[];
    __half* sA = smh;                  // [3][128][40]
    __half* sB = smh + 3 * GA_HALFS;   // [3][32][136]
    const int b = blockIdx.z;
    const __half* Xb = X + (size_t)b * 256 * HW;
    const float* Rb = EPI ? (R + (size_t)b * M * HW) : nullptr;
    const int o0 = blockIdx.y * 128;
    const int i0 = blockIdx.x * 128;
    const int tid = threadIdx.x, warp = tid >> 5, lane = tid & 31;
    const int g = lane >> 2, t = lane & 3;
    const int wm = (warp >> 1) * 32, wn = (warp & 1) * 64;

    float acc[2][8][4];
#pragma unroll
    for (int mt = 0; mt < 2; mt++)
#pragma unroll
        for (int nt = 0; nt < 8; nt++)
#pragma unroll
            for (int r = 0; r < 4; r++) acc[mt][nt][r] = 0.f;

    auto stage = [&](int ch, int buf) {
        __half* dA = sA + buf * GA_HALFS;
        __half* dB = sB + buf * GB_HALFS;
        const int c0 = ch * 32;
#pragma unroll
        for (int l = 0; l < 2; l++) {
            int idx = tid + l * 256;
            int row = idx >> 2, seg = (idx & 3) * 8;
            cpa16(dA + row * GA_PITCH + seg,
                  W + (size_t)(o0 + row) * 256 + c0 + seg);
        }
#pragma unroll
        for (int l = 0; l < 2; l++) {
            int idx = tid + l * 256;
            int row = idx >> 4, seg = (idx & 15) * 8;
            cpa16(dB + row * GB_PITCH + seg,
                  Xb + (size_t)(c0 + row) * HW + i0 + seg);
        }
    };

    const int a_row = (lane & 7) + ((lane >> 3) & 1) * 8;
    const int a_col = ((lane >> 4) & 1) * 8;
    const int b_row = (lane & 7) + ((lane >> 3) & 1) * 8;
    const int b_col = ((lane >> 4) & 1) * 8;

    stage(0, 0);
    CP_COMMIT;
    stage(1, 1);
    CP_COMMIT;

    for (int ch = 0; ch < 8; ch++) {
        if (ch == 7) { CP_WAIT(0); } else { CP_WAIT(1); }
        __syncthreads();
        if (ch + 2 < 8) {
            stage(ch + 2, (ch + 2) % 3);
            CP_COMMIT;
        }
        const __half* bA = sA + (ch % 3) * GA_HALFS;
        const __half* bB = sB + (ch % 3) * GB_HALFS;
#pragma unroll
        for (int ks = 0; ks < 2; ks++) {
            unsigned a[2][4];
#pragma unroll
            for (int mt = 0; mt < 2; mt++)
                ldsm4(a[mt], smem_u32(bA + (wm + mt * 16 + a_row) * GA_PITCH +
                                      ks * 16 + a_col));
#pragma unroll
            for (int ng = 0; ng < 4; ng++) {
                unsigned bb[4];
                ldsm4t(bb, smem_u32(bB + (ks * 16 + b_row) * GB_PITCH + wn +
                                    ng * 16 + b_col));
                mma_f16(acc[0][2 * ng], a[0], bb[0], bb[1]);
                mma_f16(acc[0][2 * ng + 1], a[0], bb[2], bb[3]);
                mma_f16(acc[1][2 * ng], a[1], bb[0], bb[1]);
                mma_f16(acc[1][2 * ng + 1], a[1], bb[2], bb[3]);
            }
        }
    }
#pragma unroll
    for (int mt = 0; mt < 2; mt++) {
#pragma unroll
        for (int nt = 0; nt < 8; nt++) {
            int row0 = o0 + wm + mt * 16 + g;
            int col = i0 + wn + nt * 8 + 2 * t;
            size_t a0 = (size_t)row0 * HW + col;
            size_t a1 = (size_t)(row0 + 8) * HW + col;
            if (HALF_OUT) {
                __half* Yh = (__half*)Yv + (size_t)b * M * HW;
                *(unsigned*)&Yh[a0] = pkhf2(acc[mt][nt][0], acc[mt][nt][1]);
                *(unsigned*)&Yh[a1] = pkhf2(acc[mt][nt][2], acc[mt][nt][3]);
            } else {
                float* Yb = (float*)Yv + (size_t)b * M * HW;
                float2 v0 = make_float2(acc[mt][nt][0], acc[mt][nt][1]);
                float2 v1 = make_float2(acc[mt][nt][2], acc[mt][nt][3]);
                if (EPI) {
                    float add0 = bias[row0], add1 = bias[row0 + 8];
                    float2 r0 = *(const float2*)&Rb[a0];
                    float2 r1 = *(const float2*)&Rb[a1];
                    v0.x += add0 + r0.x; v0.y += add0 + r0.y;
                    v1.x += add1 + r1.x; v1.y += add1 + r1.y;
                }
                *(float2*)&Yb[a0] = v0;
                *(float2*)&Yb[a1] = v1;
            }
        }
    }
}

// ==== fp16 flash attention (m32 warps, race-free 2-stage ring, 3 CTA/SM) ====
// Grid (32, 16), 128 threads = 4 warps. Warp w owns Q rows [w*32, w*32+32).
// SMEM: sK[2][64][136], sV[2][64][136] halfs; Q staged in sV stage 1.
// Ring discipline: WAIT(0) -> barrier -> stage(kt+1) -> compute(kt).
#define KV_PITCH 136
#define KV_HALFS (64 * KV_PITCH)
#define ATT_SMEM (4 * KV_HALFS * 2)
#define ONES2 0x3C003C00u

__global__ __launch_bounds__(128, 3) void attn_k() {
    extern __shared__ __half smh[];
    __half* sK0 = smh;                 // [2][64][136]
    __half* sV0 = smh + 2 * KV_HALFS;  // [2][64][136]

    const int bh = blockIdx.y;
    const int b = bh >> 2, h = bh & 3;
    const __half* Qb = g_qkv16 + ((size_t)b * 768 + h * 64) * HW;
    const __half* Kb = Qb + (size_t)256 * HW;
    const __half* Vb = Qb + (size_t)512 * HW;
    const int i0 = blockIdx.x * 128;
    const int tid = threadIdx.x;
    const int warp = tid >> 5, lane = tid & 31;
    const int g = lane >> 2, t = lane & 3;
    const int iw = warp * 32;

    const float SCL = 0.125f * 1.4426950408889634f;  // d^-0.5 * log2(e)
    const unsigned SCL2 = pkhf2(SCL, SCL);
    const unsigned NM2 = pkhf2(-4.0f, -4.0f);  // fixed log2-max offset

    auto stage_arr = [&](const __half* src, __half* dst) {
        for (int ch = tid; ch < 1024; ch += 128) {
            int d = ch >> 4, c16 = ch & 15;
            cpa16(dst + d * KV_PITCH + c16 * 8,
                  src + (size_t)d * HW + c16 * 8);
        }
    };

    // prologue: Q -> sV stage 1; tile 0 -> stage 0
    stage_arr(Qb + i0, sV0 + KV_HALFS);
    CP_COMMIT;
    stage_arr(Kb, sK0);
    stage_arr(Vb, sV0);
    CP_COMMIT;
    CP_WAIT(1);  // Q arrived (tile 0 may still be in flight)
    __syncthreads();

    // Q fragments via ldmatrix.trans from the staged [d][i] tile
    unsigned qa[2][4][4];
    {
        const __half* sQ = sV0 + KV_HALFS;
        const int drow = ((lane >> 4) & 1) * 8 + (lane & 7);
        const int jsel = ((lane >> 3) & 1) * 8;
#pragma unroll
        for (int mt = 0; mt < 2; mt++)
#pragma unroll
            for (int ks = 0; ks < 4; ks++)
                ldsm4t(qa[mt][ks], smem_u32(sQ + (ks * 16 + drow) * KV_PITCH +
                                            iw + mt * 16 + jsel));
    }
    // NOTE: no barrier needed here for Q: the loop's first iteration does
    // WAIT(0) + __syncthreads() BEFORE staging tile 1 over the Q buffer.

    float o[2][8][4];
#pragma unroll
    for (int mt = 0; mt < 2; mt++)
#pragma unroll
        for (int dt = 0; dt < 8; dt++)
#pragma unroll
            for (int r = 0; r < 4; r++) o[mt][dt][r] = 0.f;
    float co[2][4] = {{0.f, 0.f, 0.f, 0.f}, {0.f, 0.f, 0.f, 0.f}};

    const int s_drow = ((lane >> 3) & 1) * 8 + (lane & 7);
    const int s_joff = ((lane >> 4) & 1) * 8;
    const int v_drow = ((lane >> 4) & 1) * 8 + (lane & 7);
    const int v_joff = ((lane >> 3) & 1) * 8;

    for (int kt = 0; kt < 32; kt++) {
        // tile kt is the only committed group still outstanding
        CP_WAIT(0);
        __syncthreads();  // kt visible to all; all warps done with kt-1 (and Q)
        if (kt + 1 < 32) {
            // overwrites buffer of tile kt-1 (safe after the barrier);
            // copy flies while we compute tile kt below
            stage_arr(Kb + (kt + 1) * 128, sK0 + ((kt + 1) & 1) * KV_HALFS);
            stage_arr(Vb + (kt + 1) * 128, sV0 + ((kt + 1) & 1) * KV_HALFS);
            CP_COMMIT;
        }
        const __half* sK = sK0 + (kt & 1) * KV_HALFS;
        const __half* sV = sV0 + (kt & 1) * KV_HALFS;

        // ---- jg-interleaved: 8 independent 16-column slices ----
#pragma unroll
        for (int jg = 0; jg < 8; jg++) {
            float c[2][2][4];
#pragma unroll
            for (int mt = 0; mt < 2; mt++)
#pragma unroll
                for (int n8 = 0; n8 < 2; n8++)
#pragma unroll
                    for (int r = 0; r < 4; r++) c[mt][n8][r] = 0.f;
#pragma unroll
            for (int ks = 0; ks < 4; ks++) {
                unsigned kb[4];
                ldsm4t(kb, smem_u32(sK + (ks * 16 + s_drow) * KV_PITCH +
                                    jg * 16 + s_joff));
                mma_f16(c[0][0], qa[0][ks], kb[0], kb[1]);
                mma_f16(c[0][1], qa[0][ks], kb[2], kb[3]);
                mma_f16(c[1][0], qa[1][ks], kb[0], kb[1]);
                mma_f16(c[1][1], qa[1][ks], kb[2], kb[3]);
            }

            unsigned pa[2][4];
#pragma unroll
            for (int mt = 0; mt < 2; mt++) {
                pa[mt][0] = h2ex2u(hfma2u(
                    pkhf2(c[mt][0][0], c[mt][0][1]), SCL2, NM2));
                pa[mt][1] = h2ex2u(hfma2u(
                    pkhf2(c[mt][0][2], c[mt][0][3]), SCL2, NM2));
                pa[mt][2] = h2ex2u(hfma2u(
                    pkhf2(c[mt][1][0], c[mt][1][1]), SCL2, NM2));
                pa[mt][3] = h2ex2u(hfma2u(
                    pkhf2(c[mt][1][2], c[mt][1][3]), SCL2, NM2));
            }

            mma_f16(co[0], pa[0], ONES2, ONES2);
            mma_f16(co[1], pa[1], ONES2, ONES2);
#pragma unroll
            for (int dtp = 0; dtp < 4; dtp++) {
                unsigned vb[4];
                ldsm4(vb, smem_u32(sV + (dtp * 16 + v_drow) * KV_PITCH +
                                   jg * 16 + v_joff));
                mma_f16(o[0][2 * dtp], pa[0], vb[0], vb[1]);
                mma_f16(o[0][2 * dtp + 1], pa[0], vb[2], vb[3]);
                mma_f16(o[1][2 * dtp], pa[1], vb[0], vb[1]);
                mma_f16(o[1][2 * dtp + 1], pa[1], vb[2], vb[3]);
            }
        }
    }

    // ---- epilogue: O/l -> g_att16 ----
    const size_t cb = ((size_t)b * 256 + h * 64);
#pragma unroll
    for (int mt = 0; mt < 2; mt++) {
        float inv0 = 1.f / co[mt][0], inv1 = 1.f / co[mt][2];
        const int ib = i0 + iw + mt * 16 + g;
#pragma unroll
        for (int dt = 0; dt < 8; dt++) {
            int d0 = dt * 8 + 2 * t;
            size_t r0a = (cb + d0) * HW + ib;
            size_t r1a = (cb + d0 + 1) * HW + ib;
            g_att16[r0a] = __float2half(o[mt][dt][0] * inv0);
            g_att16[r1a] = __float2half(o[mt][dt][1] * inv0);
            g_att16[r0a + 8] = __float2half(o[mt][dt][2] * inv1);
            g_att16[r1a + 8] = __float2half(o[mt][dt][3] * inv1);
        }
    }
}

// ---------------- launch ----------------
extern "C" void kernel_launch(void* const* d_in, const int* in_sizes, int n_in,
                              void* d_out, int out_size) {
    (void)in_sizes; (void)n_in; (void)out_size;
    const float* x     = (const float*)d_in[0];
    const float* w_qkv = (const float*)d_in[1];
    const float* w_out = (const float*)d_in[2];
    const float* b_out = (const float*)d_in[3];
    float* out = (float*)d_out;

    void *x16p, *wq16p, *wo16p, *qkv16p, *att16p;
    cudaGetSymbolAddress(&x16p, g_x16);
    cudaGetSymbolAddress(&wq16p, g_wq16);
    cudaGetSymbolAddress(&wo16p, g_wo16);
    cudaGetSymbolAddress(&qkv16p, g_qkv16);
    cudaGetSymbolAddress(&att16p, g_att16);

    cudaFuncSetAttribute(gemm_f16<768, false, true>,
                         cudaFuncAttributeMaxDynamicSharedMemorySize,
                         (int)GEMM_SMEM);
    cudaFuncSetAttribute(gemm_f16<256, true, false>,
                         cudaFuncAttributeMaxDynamicSharedMemorySize,
                         (int)GEMM_SMEM);
    cudaFuncSetAttribute(attn_k, cudaFuncAttributeMaxDynamicSharedMemorySize,
                         (int)ATT_SMEM);

    cvt3_k<<<(CVT_TOT + 255) / 256, 256>>>(x, (__half*)x16p, w_qkv,
                                           (__half*)wq16p, w_out,
                                           (__half*)wo16p);

    gemm_f16<768, false, true><<<dim3(32, 6, 4), 256, GEMM_SMEM>>>(
        (const __half*)wq16p, (const __half*)x16p, nullptr, nullptr, qkv16p);
    attn_k<<<dim3(32, 16), 128, ATT_SMEM>>>();
    gemm_f16<256, true, false><<<dim3(32, 2, 4), 256, GEMM_SMEM>>>(
        (const __half*)wo16p, (const __half*)att16p, b_out, x, out);
}